// round 16
// baseline (speedup 1.0000x reference)
#include <cuda_runtime.h>
#include <cuda_fp16.h>
#include <cstdint>

#define EMBED 1024
#define NHEAD 16
#define HDIM  64
#define BATCH 2
#define SEQ   2048
#define MROWS (BATCH*SEQ)   // 4096

// tf32-rounded copies of inputs / weights
__device__ float g_qc[MROWS*EMBED];
__device__ float g_kc[MROWS*EMBED];
__device__ float g_vc[MROWS*EMBED];
__device__ float g_w4[4*EMBED*EMBED];         // Wq | Wk | Wv | Wo
// fp16 hi/lo projections: Q,K in [B,H,T,D]; V in [B,H,D,T] (transposed)
__device__ __half g_qh[BATCH*NHEAD*SEQ*HDIM];
__device__ __half g_ql[BATCH*NHEAD*SEQ*HDIM];
__device__ __half g_kh[BATCH*NHEAD*SEQ*HDIM];
__device__ __half g_kl[BATCH*NHEAD*SEQ*HDIM];
__device__ __half g_vh[BATCH*NHEAD*SEQ*HDIM];
__device__ __half g_vl[BATCH*NHEAD*SEQ*HDIM];
__device__ float g_maskf[BATCH*SEQ];          // 0 or -1e30
__device__ float g_ao[MROWS*EMBED];           // attention out, [B,T,E] (tf32-rounded)

__device__ __forceinline__ uint32_t f2tf32(float x) {
    uint32_t r;
    asm("cvt.rna.tf32.f32 %0, %1;" : "=r"(r) : "f"(x));
    return r;
}

__device__ __forceinline__ uint32_t smem_u32(const void* p) {
    uint32_t a;
    asm("{ .reg .u64 t; cvta.to.shared.u64 t, %1; cvt.u32.u64 %0, t; }" : "=r"(a) : "l"(p));
    return a;
}

// ---------------------------------------------------------------------------
// Prepass: tf32-round inputs + weights; float mask.
// ---------------------------------------------------------------------------
__global__ __launch_bounds__(256) void prepass(
    const float* __restrict__ q, const float* __restrict__ k, const float* __restrict__ v,
    const float* __restrict__ Wq, const float* __restrict__ Wk,
    const float* __restrict__ Wv, const float* __restrict__ Wo)
{
    int idx = blockIdx.x * 256 + threadIdx.x;       // float4 index
    const float* src; float* dst; int off;
    if (idx < 3145728) {
        int seg = idx >> 20;
        off = idx & 1048575;
        src = (seg == 0) ? q : (seg == 1) ? k : v;
        dst = (seg == 0) ? g_qc : (seg == 1) ? g_kc : g_vc;
    } else {
        int r = idx - 3145728;
        int seg = r >> 18;
        off = r & 262143;
        src = (seg == 0) ? Wq : (seg == 1) ? Wk : (seg == 2) ? Wv : Wo;
        dst = g_w4 + (size_t)seg * EMBED * EMBED;
    }
    float4 x = reinterpret_cast<const float4*>(src)[off];
    uint4 t = make_uint4(f2tf32(x.x), f2tf32(x.y), f2tf32(x.z), f2tf32(x.w));
    reinterpret_cast<uint4*>(dst)[off] = t;
}

__global__ __launch_bounds__(256) void mask_prep(const unsigned char* __restrict__ kpm)
{
    int i = blockIdx.x * 256 + threadIdx.x;
    if (i < BATCH*SEQ) g_maskf[i] = kpm[i] ? -1e30f : 0.0f;
}

// ---------------------------------------------------------------------------
// TF32 GEMM (R15): 128 threads, 4 warps of 64x64 tiles, 2-stage cp.async.
// mode: 0 = fp32 [M,E]; 1 = fp16 hi/lo [B,H,T,D]; 2 = fp16 hi/lo [B,H,D,T].
// ---------------------------------------------------------------------------
__device__ __forceinline__ void mma_tf32(float* c, const uint32_t* a,
                                         uint32_t b0, uint32_t b1) {
    asm volatile(
        "mma.sync.aligned.m16n8k8.row.col.f32.tf32.tf32.f32 "
        "{%0,%1,%2,%3}, {%4,%5,%6,%7}, {%8,%9}, {%0,%1,%2,%3};"
        : "+f"(c[0]), "+f"(c[1]), "+f"(c[2]), "+f"(c[3])
        : "r"(a[0]), "r"(a[1]), "r"(a[2]), "r"(a[3]), "r"(b0), "r"(b1));
}

#define GP 36
#define GA_WORDS (128*GP)
#define GSTAGE   (2*GA_WORDS)
#define GEMM_SMEM (2*GSTAGE*4)   // 73728

__device__ __forceinline__ void gemm_body(
    const float* __restrict__ A, const float* __restrict__ W,
    const float* __restrict__ bias, float* __restrict__ Cf,
    __half* __restrict__ Ch, __half* __restrict__ Cl,
    int m0, int n0, int mode)
{
    const int K = EMBED;
    extern __shared__ uint32_t gsm[];
    uint32_t sbase = smem_u32(gsm);

    int tid  = threadIdx.x;
    int lane = tid & 31;
    int warp = tid >> 5;                 // 0..3
    int m0w = (warp >> 1) * 64;
    int n0w = (warp & 1) * 64;

    float c[4][8][4];
    #pragma unroll
    for (int mi = 0; mi < 4; mi++)
        #pragma unroll
        for (int ni = 0; ni < 8; ni++)
            #pragma unroll
            for (int q = 0; q < 4; q++) c[mi][ni][q] = 0.f;

    auto issue = [&](int k0, int s) {
        #pragma unroll
        for (int i = 0; i < 8; i++) {
            int idx = tid + i*128;
            int r = idx >> 3, c4 = (idx & 7) << 2;
            uint32_t da = sbase + (uint32_t)(s*GSTAGE + r*GP + c4) * 4u;
            const float* ga = A + (size_t)(m0 + r) * K + k0 + c4;
            asm volatile("cp.async.cg.shared.global [%0], [%1], 16;" :: "r"(da), "l"(ga));
            uint32_t dw = da + GA_WORDS * 4u;
            const float* gw = W + (size_t)(n0 + r) * K + k0 + c4;
            asm volatile("cp.async.cg.shared.global [%0], [%1], 16;" :: "r"(dw), "l"(gw));
        }
        asm volatile("cp.async.commit_group;" ::: "memory");
    };

    issue(0, 0);

    const int NCHUNK = K / 32;   // 32
    for (int ch = 0; ch < NCHUNK; ch++) {
        asm volatile("cp.async.wait_group 0;" ::: "memory");
        __syncthreads();
        if (ch + 1 < NCHUNK) issue((ch + 1) * 32, (ch + 1) & 1);

        const uint32_t* As = gsm + (ch & 1) * GSTAGE;
        const uint32_t* Ws = As + GA_WORDS;
        #pragma unroll
        for (int kk = 0; kk < 32; kk += 8) {
            int kb = kk + (lane & 3);
            uint32_t a[4][4];
            #pragma unroll
            for (int mi = 0; mi < 4; mi++) {
                int r = m0w + mi * 16 + (lane >> 2);
                a[mi][0] = As[r*GP + kb];
                a[mi][1] = As[(r + 8)*GP + kb];
                a[mi][2] = As[r*GP + kb + 4];
                a[mi][3] = As[(r + 8)*GP + kb + 4];
            }
            #pragma unroll
            for (int ni = 0; ni < 8; ni++) {
                int rn = n0w + ni * 8 + (lane >> 2);
                uint32_t b0 = Ws[rn*GP + kb];
                uint32_t b1 = Ws[rn*GP + kb + 4];
                #pragma unroll
                for (int mi = 0; mi < 4; mi++)
                    mma_tf32(c[mi][ni], a[mi], b0, b1);
            }
        }
        __syncthreads();
    }

    #pragma unroll
    for (int mi = 0; mi < 4; mi++) {
        int rbase = m0 + m0w + mi * 16 + (lane >> 2);
        #pragma unroll
        for (int ni = 0; ni < 8; ni++) {
            int col = n0 + n0w + ni * 8 + 2 * (lane & 3);    // even
            float bv0 = bias[col], bv1 = bias[col + 1];
            #pragma unroll
            for (int half = 0; half < 2; half++) {
                int m = rbase + half * 8;
                float v0 = c[mi][ni][half * 2 + 0] + bv0;
                float v1 = c[mi][ni][half * 2 + 1] + bv1;
                if (mode == 0) {
                    Cf[(size_t)m * EMBED + col]     = v0;
                    Cf[(size_t)m * EMBED + col + 1] = v1;
                } else {
                    int bb = m >> 11, t = m & 2047;
                    int hh = col >> 6, d = col & 63;
                    __half h0 = __float2half(v0), h1 = __float2half(v1);
                    __half l0v = __float2half(v0 - __half2float(h0));
                    __half l1v = __float2half(v1 - __half2float(h1));
                    if (mode == 1) {
                        size_t base = (((size_t)(bb * NHEAD + hh)) * SEQ + t) * HDIM + d;
                        __half2 hp = __halves2half2(h0, h1);
                        __half2 lp = __halves2half2(l0v, l1v);
                        reinterpret_cast<uint32_t*>(Ch)[base >> 1] = *reinterpret_cast<uint32_t*>(&hp);
                        reinterpret_cast<uint32_t*>(Cl)[base >> 1] = *reinterpret_cast<uint32_t*>(&lp);
                    } else {   // mode 2: transposed [B,H,D,T]
                        size_t o0 = (((size_t)(bb * NHEAD + hh)) * HDIM + d) * SEQ + t;
                        Ch[o0]       = h0;
                        Ch[o0 + SEQ] = h1;
                        Cl[o0]       = l0v;
                        Cl[o0 + SEQ] = l1v;
                    }
                }
            }
        }
    }
}

__global__ __launch_bounds__(128) void gemm_qkv(
    const float* __restrict__ bq, const float* __restrict__ bk, const float* __restrict__ bv)
{
    int z = blockIdx.z;
    const float* A = (z == 0) ? g_qc : (z == 1) ? g_kc : g_vc;
    const float* W = g_w4 + (size_t)z * EMBED * EMBED;
    const float* B = (z == 0) ? bq : (z == 1) ? bk : bv;
    __half* Ch = (z == 0) ? g_qh : (z == 1) ? g_kh : g_vh;
    __half* Cl = (z == 0) ? g_ql : (z == 1) ? g_kl : g_vl;
    gemm_body(A, W, B, nullptr, Ch, Cl, blockIdx.y * 128, blockIdx.x * 128,
              (z == 2) ? 2 : 1);
}

__global__ __launch_bounds__(128) void gemm_out(
    const float* __restrict__ bias, float* __restrict__ C)
{
    gemm_body(g_ao, g_w4 + (size_t)3 * EMBED * EMBED, bias, C,
              nullptr, nullptr, blockIdx.y * 128, blockIdx.x * 128, 0);
}

// ---------------------------------------------------------------------------
// Flash attention v3: 128 threads / 64 Q-rows per CTA -> 2 CTAs/SM; phases of
// the two resident CTAs interleave (softmax of one overlaps mma of other).
// fp16 split mma; ex2.approx.f16x2; l via ones-mma; 2-stage cp.async staging.
// ---------------------------------------------------------------------------
__device__ __forceinline__ void mma_f16(float* c, const uint32_t* a,
                                        uint32_t b0, uint32_t b1) {
    asm volatile(
        "mma.sync.aligned.m16n8k16.row.col.f32.f16.f16.f32 "
        "{%0,%1,%2,%3}, {%4,%5,%6,%7}, {%8,%9}, {%0,%1,%2,%3};"
        : "+f"(c[0]), "+f"(c[1]), "+f"(c[2]), "+f"(c[3])
        : "r"(a[0]), "r"(a[1]), "r"(a[2]), "r"(a[3]), "r"(b0), "r"(b1));
}

#define FPITCH 72
#define FSM_STAGE0   18432        // Q region: 64 rows * 144B * 2 (Qh+Ql)
#define FSM_STAGE_SZ 36864        // Kh,Kl,Vh,Vl: 4 * 64 * 144B
#define FSM_REG      9216
#define FSM_MASK     (FSM_STAGE0 + 2*FSM_STAGE_SZ)   // 92160
#define FLASH_SMEM   (FSM_MASK + 2*256)              // 92672

__global__ __launch_bounds__(128) void flash_attn_mma()
{
    extern __shared__ __align__(16) char smraw[];
    __half* sQh = (__half*)smraw;
    __half* sQl = sQh + 64*FPITCH;
    uint32_t sb = smem_u32(smraw);

    int tid  = threadIdx.x;
    int lane = tid & 31, warp = tid >> 5;          // warp 0..3
    int grp  = lane >> 2, thr4 = lane & 3;
    int qt = (int)gridDim.x - 1 - (int)blockIdx.x;  // heavy tiles first
    int h = blockIdx.y, b = blockIdx.z;
    int qbase = qt * 64;

    size_t headoff = ((size_t)(b*NHEAD + h))*SEQ*HDIM;
    const uint32_t* Qh32 = (const uint32_t*)g_qh + (headoff + (size_t)qbase*HDIM)/2;
    const uint32_t* Ql32 = (const uint32_t*)g_ql + (headoff + (size_t)qbase*HDIM)/2;
    const char* khg = (const char*)g_kh + headoff*2;
    const char* klg = (const char*)g_kl + headoff*2;
    const char* vhg = (const char*)g_vh + headoff*2;   // [D][T] layout
    const char* vlg = (const char*)g_vl + headoff*2;
    const char* mfg = (const char*)(g_maskf + (size_t)b*SEQ);

    const int ntiles = qt + 1;   // causal: key tiles 0..qt

    auto issue = [&](int jt) {
        int st = jt & 1;
        int s0 = jt * 64;
        uint32_t base = sb + FSM_STAGE0 + st*FSM_STAGE_SZ;
        #pragma unroll
        for (int i = 0; i < 4; i++) {
            int c = tid + i*128;            // 0..511
            int row = c >> 3;
            int o16 = (c & 7) * 16;
            uint32_t doff = (uint32_t)(row*144 + o16);
            const char* ksrc = khg + (size_t)(s0 + row)*128 + o16;
            asm volatile("cp.async.cg.shared.global [%0], [%1], 16;" :: "r"(base + doff), "l"(ksrc));
            const char* ksrc2 = klg + (size_t)(s0 + row)*128 + o16;
            asm volatile("cp.async.cg.shared.global [%0], [%1], 16;" :: "r"(base + FSM_REG + doff), "l"(ksrc2));
            const char* vsrc = vhg + (size_t)row*(SEQ*2) + s0*2 + o16;
            asm volatile("cp.async.cg.shared.global [%0], [%1], 16;" :: "r"(base + 2*FSM_REG + doff), "l"(vsrc));
            const char* vsrc2 = vlg + (size_t)row*(SEQ*2) + s0*2 + o16;
            asm volatile("cp.async.cg.shared.global [%0], [%1], 16;" :: "r"(base + 3*FSM_REG + doff), "l"(vsrc2));
        }
        if (tid < 16) {
            uint32_t dm = sb + FSM_MASK + st*256 + tid*16;
            const char* ms = mfg + (size_t)s0*4 + tid*16;
            asm volatile("cp.async.cg.shared.global [%0], [%1], 16;" :: "r"(dm), "l"(ms));
        }
        asm volatile("cp.async.commit_group;" ::: "memory");
    };

    issue(0);

    // ---- stage Q (64 rows, pure copy) ----
    #pragma unroll
    for (int i = 0; i < 8; i++) {
        int e = tid + i*128;                 // 0..1023
        int r = e >> 4, c4 = (e & 15) << 2;
        int gi = (r*HDIM + c4) >> 1;
        *reinterpret_cast<uint2*>(sQh + r*FPITCH + c4) = *reinterpret_cast<const uint2*>(Qh32 + gi);
        *reinterpret_cast<uint2*>(sQl + r*FPITCH + c4) = *reinterpret_cast<const uint2*>(Ql32 + gi);
    }
    __syncthreads();

    // ---- preload Q fragments ----
    uint32_t qh[4][4], ql[4][4];
    {
        int rl = warp*16 + grp;
        #pragma unroll
        for (int ks = 0; ks < 4; ks++) {
            int cc = thr4*2 + ks*16;
            qh[ks][0] = *(const uint32_t*)(sQh + rl*FPITCH + cc);
            qh[ks][1] = *(const uint32_t*)(sQh + (rl+8)*FPITCH + cc);
            qh[ks][2] = *(const uint32_t*)(sQh + rl*FPITCH + cc + 8);
            qh[ks][3] = *(const uint32_t*)(sQh + (rl+8)*FPITCH + cc + 8);
            ql[ks][0] = *(const uint32_t*)(sQl + rl*FPITCH + cc);
            ql[ks][1] = *(const uint32_t*)(sQl + (rl+8)*FPITCH + cc);
            ql[ks][2] = *(const uint32_t*)(sQl + rl*FPITCH + cc + 8);
            ql[ks][3] = *(const uint32_t*)(sQl + (rl+8)*FPITCH + cc + 8);
        }
    }

    int row0 = qbase + warp*16 + grp;
    int row1 = row0 + 8;

    float m0 = -1e30f, m1 = -1e30f, l0 = 0.f, l1 = 0.f;
    float o[8][4];
    #pragma unroll
    for (int j = 0; j < 8; j++)
        #pragma unroll
        for (int q = 0; q < 4; q++) o[j][q] = 0.f;

    const float L2E = 1.4426950408889634f;
    const uint32_t ONES2 = 0x3C003C00u;   // {1.0h, 1.0h}

    for (int jt = 0; jt < ntiles; jt++) {
        int s0 = jt * 64;
        int st = jt & 1;
        asm volatile("cp.async.wait_group 0;" ::: "memory");
        __syncthreads();
        if (jt + 1 < ntiles) issue(jt + 1);

        __half* sKh = (__half*)(smraw + FSM_STAGE0 + st*FSM_STAGE_SZ);
        __half* sKl = sKh + FSM_REG/2;
        __half* sVh = sKh + FSM_REG;
        __half* sVl = sKh + 3*FSM_REG/2;
        float* mfs = (float*)(smraw + FSM_MASK + st*256);

        // ---- S = Q K^T (fp16 split, 3 terms) ----
        float s[8][4];
        #pragma unroll
        for (int j = 0; j < 8; j++)
            #pragma unroll
            for (int q = 0; q < 4; q++) s[j][q] = 0.f;

        #pragma unroll
        for (int ks = 0; ks < 4; ks++) {
            int cc = thr4*2 + ks*16;
            #pragma unroll
            for (int j = 0; j < 8; j++) {
                int n = j*8 + grp;
                uint32_t bh0 = *(const uint32_t*)(sKh + n*FPITCH + cc);
                uint32_t bh1 = *(const uint32_t*)(sKh + n*FPITCH + cc + 8);
                uint32_t bl0 = *(const uint32_t*)(sKl + n*FPITCH + cc);
                uint32_t bl1 = *(const uint32_t*)(sKl + n*FPITCH + cc + 8);
                mma_f16(s[j], qh[ks], bh0, bh1);
                mma_f16(s[j], qh[ks], bl0, bl1);
                mma_f16(s[j], ql[ks], bh0, bh1);
            }
        }

        // ---- scale + masks + row max ----
        bool diag = (jt == qt);
        float nm0 = m0, nm1 = m1;
        #pragma unroll
        for (int j = 0; j < 8; j++) {
            int cb = 8*j + 2*thr4;
            float f0 = mfs[cb], f1 = mfs[cb+1];
            float v00 = fmaf(s[j][0], 0.125f, f0);
            float v01 = fmaf(s[j][1], 0.125f, f1);
            float v10 = fmaf(s[j][2], 0.125f, f0);
            float v11 = fmaf(s[j][3], 0.125f, f1);
            if (diag) {
                int ca = s0 + cb;
                if (ca     > row0) v00 = -1e30f;
                if (ca + 1 > row0) v01 = -1e30f;
                if (ca     > row1) v10 = -1e30f;
                if (ca + 1 > row1) v11 = -1e30f;
            }
            s[j][0] = v00; s[j][1] = v01; s[j][2] = v10; s[j][3] = v11;
            nm0 = fmaxf(nm0, fmaxf(v00, v01));
            nm1 = fmaxf(nm1, fmaxf(v10, v11));
        }
        nm0 = fmaxf(nm0, __shfl_xor_sync(0xffffffffu, nm0, 1));
        nm0 = fmaxf(nm0, __shfl_xor_sync(0xffffffffu, nm0, 2));
        nm1 = fmaxf(nm1, __shfl_xor_sync(0xffffffffu, nm1, 1));
        nm1 = fmaxf(nm1, __shfl_xor_sync(0xffffffffu, nm1, 2));

        float c0 = __expf(m0 - nm0), c1 = __expf(m1 - nm1);
        m0 = nm0; m1 = nm1;
        float mb0 = m0 * L2E, mb1 = m1 * L2E;

        // ---- P = exp(s - m): fp16x2 ex2, output directly packed ----
        uint32_t pr[8], ps[8];
        #pragma unroll
        for (int j = 0; j < 8; j++) {
            float t00 = fmaf(s[j][0], L2E, -mb0);
            float t01 = fmaf(s[j][1], L2E, -mb0);
            float t10 = fmaf(s[j][2], L2E, -mb1);
            float t11 = fmaf(s[j][3], L2E, -mb1);
            uint32_t ta, tb;
            asm("cvt.rn.f16x2.f32 %0, %1, %2;" : "=r"(ta) : "f"(t01), "f"(t00));
            asm("cvt.rn.f16x2.f32 %0, %1, %2;" : "=r"(tb) : "f"(t11), "f"(t10));
            asm("ex2.approx.f16x2 %0, %1;" : "=r"(pr[j]) : "r"(ta));
            asm("ex2.approx.f16x2 %0, %1;" : "=r"(ps[j]) : "r"(tb));
        }

        // ---- l sums via ones-mma ----
        float lacc[4] = {0.f, 0.f, 0.f, 0.f};
        #pragma unroll
        for (int ks = 0; ks < 4; ks++) {
            uint32_t a[4] = {pr[2*ks], ps[2*ks], pr[2*ks+1], ps[2*ks+1]};
            mma_f16(lacc, a, ONES2, ONES2);
        }
        l0 = l0*c0 + lacc[0];
        l1 = l1*c1 + lacc[2];

        #pragma unroll
        for (int j = 0; j < 8; j++) {
            o[j][0] *= c0; o[j][1] *= c0;
            o[j][2] *= c1; o[j][3] *= c1;
        }

        // ---- O += P V (2 terms) ----
        #pragma unroll
        for (int ks = 0; ks < 4; ks++) {
            uint32_t a[4] = {pr[2*ks], ps[2*ks], pr[2*ks+1], ps[2*ks+1]};
            int cc = thr4*2 + ks*16;
            #pragma unroll
            for (int j = 0; j < 8; j++) {
                int n = j*8 + grp;
                uint32_t vh0 = *(const uint32_t*)(sVh + n*FPITCH + cc);
                uint32_t vh1 = *(const uint32_t*)(sVh + n*FPITCH + cc + 8);
                uint32_t vl0 = *(const uint32_t*)(sVl + n*FPITCH + cc);
                uint32_t vl1 = *(const uint32_t*)(sVl + n*FPITCH + cc + 8);
                mma_f16(o[j], a, vh0, vh1);
                mma_f16(o[j], a, vl0, vl1);
            }
        }
    }

    // ---- epilogue: [B,T,E], pre-rounded to tf32 for gemm_out ----
    float inv0 = 1.f / l0, inv1 = 1.f / l1;
    float* O0 = g_ao + ((size_t)(b*SEQ) + row0)*EMBED + h*HDIM;
    float* O1 = g_ao + ((size_t)(b*SEQ) + row1)*EMBED + h*HDIM;
    #pragma unroll
    for (int j = 0; j < 8; j++) {
        int col = 8*j + 2*thr4;
        uint2 r0 = make_uint2(f2tf32(o[j][0]*inv0), f2tf32(o[j][1]*inv0));
        uint2 r1 = make_uint2(f2tf32(o[j][2]*inv1), f2tf32(o[j][3]*inv1));
        *reinterpret_cast<uint2*>(O0 + col) = r0;
        *reinterpret_cast<uint2*>(O1 + col) = r1;
    }
}

// ---------------------------------------------------------------------------
extern "C" void kernel_launch(void* const* d_in, const int* in_sizes, int n_in,
                              void* d_out, int out_size)
{
    const float* query = (const float*)d_in[0];
    const float* key   = (const float*)d_in[1];
    const float* value = (const float*)d_in[2];
    const unsigned char* kpm = (const unsigned char*)d_in[3];
    const float* Wq = (const float*)d_in[4];
    const float* bq = (const float*)d_in[5];
    const float* Wk = (const float*)d_in[6];
    const float* bk = (const float*)d_in[7];
    const float* Wv = (const float*)d_in[8];
    const float* bv = (const float*)d_in[9];
    const float* Wo = (const float*)d_in[10];
    const float* bo = (const float*)d_in[11];
    float* out = (float*)d_out;

    prepass<<<16384, 256>>>(query, key, value, Wq, Wk, Wv, Wo);
    mask_prep<<<16, 256>>>(kpm);

    cudaFuncSetAttribute(gemm_qkv, cudaFuncAttributeMaxDynamicSharedMemorySize, GEMM_SMEM);
    cudaFuncSetAttribute(gemm_out, cudaFuncAttributeMaxDynamicSharedMemorySize, GEMM_SMEM);

    dim3 gqkv(EMBED/128, MROWS/128, 3);   // (8, 32, 3)
    gemm_qkv<<<gqkv, 128, GEMM_SMEM>>>(bq, bk, bv);

    cudaFuncSetAttribute(flash_attn_mma, cudaFuncAttributeMaxDynamicSharedMemorySize, FLASH_SMEM);
    flash_attn_mma<<<dim3(SEQ/64, NHEAD, BATCH), 128, FLASH_SMEM>>>();

    dim3 gout(EMBED/128, MROWS/128);
    gemm_out<<<gout, 128, GEMM_SMEM>>>(bo, out);
}

// round 17
// speedup vs baseline: 1.3177x; 1.3177x over previous
#include <cuda_runtime.h>
#include <cuda_fp16.h>
#include <cstdint>

#define EMBED 1024
#define NHEAD 16
#define HDIM  64
#define BATCH 2
#define SEQ   2048
#define MROWS (BATCH*SEQ)   // 4096

// fp16-rounded (11-bit significand == tf32 precision for O(1) data) copies
__device__ __half g_qc[MROWS*EMBED];
__device__ __half g_kc[MROWS*EMBED];
__device__ __half g_vc[MROWS*EMBED];
__device__ __half g_w4[4*EMBED*EMBED];        // Wq | Wk | Wv | Wo
// fp16 hi/lo projections: Q,K in [B,H,T,D]; V in [B,H,D,T] (transposed)
__device__ __half g_qh[BATCH*NHEAD*SEQ*HDIM];
__device__ __half g_ql[BATCH*NHEAD*SEQ*HDIM];
__device__ __half g_kh[BATCH*NHEAD*SEQ*HDIM];
__device__ __half g_kl[BATCH*NHEAD*SEQ*HDIM];
__device__ __half g_vh[BATCH*NHEAD*SEQ*HDIM];
__device__ __half g_vl[BATCH*NHEAD*SEQ*HDIM];
__device__ float g_maskf[BATCH*SEQ];          // 0 or -1e30
__device__ float g_ao[MROWS*EMBED];           // attention out, [B,T,E] (hi/lo split input to gemm_out via fp16 pair)
__device__ __half g_aoh[MROWS*EMBED];         // attention out hi (fp16)
__device__ __half g_aol[MROWS*EMBED];         // attention out lo (fp16)

__device__ __forceinline__ uint32_t smem_u32(const void* p) {
    uint32_t a;
    asm("{ .reg .u64 t; cvta.to.shared.u64 t, %1; cvt.u32.u64 %0, t; }" : "=r"(a) : "l"(p));
    return a;
}

__device__ __forceinline__ uint32_t packh2(float x, float y) {
    uint32_t r;
    asm("cvt.rn.f16x2.f32 %0, %1, %2;" : "=r"(r) : "f"(y), "f"(x));
    return r;
}

// ---------------------------------------------------------------------------
// Prepass: round inputs + weights to fp16; float mask.
// ---------------------------------------------------------------------------
__global__ __launch_bounds__(256) void prepass(
    const float* __restrict__ q, const float* __restrict__ k, const float* __restrict__ v,
    const float* __restrict__ Wq, const float* __restrict__ Wk,
    const float* __restrict__ Wv, const float* __restrict__ Wo)
{
    int idx = blockIdx.x * 256 + threadIdx.x;       // float4 index
    const float* src; __half* dst; int off;
    if (idx < 3145728) {
        int seg = idx >> 20;
        off = idx & 1048575;
        src = (seg == 0) ? q : (seg == 1) ? k : v;
        dst = (seg == 0) ? g_qc : (seg == 1) ? g_kc : g_vc;
    } else {
        int r = idx - 3145728;
        int seg = r >> 18;
        off = r & 262143;
        src = (seg == 0) ? Wq : (seg == 1) ? Wk : (seg == 2) ? Wv : Wo;
        dst = g_w4 + (size_t)seg * EMBED * EMBED;
    }
    float4 x = reinterpret_cast<const float4*>(src)[off];
    uint2 t = make_uint2(packh2(x.x, x.y), packh2(x.z, x.w));
    reinterpret_cast<uint2*>(dst)[off] = t;
}

__global__ __launch_bounds__(256) void mask_prep(const unsigned char* __restrict__ kpm)
{
    int i = blockIdx.x * 256 + threadIdx.x;
    if (i < BATCH*SEQ) g_maskf[i] = kpm[i] ? -1e30f : 0.0f;
}

// ---------------------------------------------------------------------------
// fp16 GEMM: C = A @ W^T + bias. Inputs fp16 (exactly 11-bit rounded fp32).
// Single-term m16n8k16 (exact products, fp32 accum) -> half the mma count of
// tf32. 128 threads, 4 warps, 64x64 warp tiles, BK=64, 2-stage cp.async.
// mode: 0 = fp32 [M,E]; 1 = fp16 hi/lo [B,H,T,D]; 2 = fp16 hi/lo [B,H,D,T].
// ---------------------------------------------------------------------------
__device__ __forceinline__ void mma_f16(float* c, const uint32_t* a,
                                        uint32_t b0, uint32_t b1) {
    asm volatile(
        "mma.sync.aligned.m16n8k16.row.col.f32.f16.f16.f32 "
        "{%0,%1,%2,%3}, {%4,%5,%6,%7}, {%8,%9}, {%0,%1,%2,%3};"
        : "+f"(c[0]), "+f"(c[1]), "+f"(c[2]), "+f"(c[3])
        : "r"(a[0]), "r"(a[1]), "r"(a[2]), "r"(a[3]), "r"(b0), "r"(b1));
}

#define GHPITCH 72                 // halves per row: 128B data + 16B pad
#define GAREG_B  18432             // 128 rows * 144B
#define GSTAGE_B 36864             // A + W
#define GEMM_SMEM (2*GSTAGE_B)     // 73728

__device__ __forceinline__ void gemm_body(
    const __half* __restrict__ A, const __half* __restrict__ W,
    const float* __restrict__ bias, float* __restrict__ Cf,
    __half* __restrict__ Ch, __half* __restrict__ Cl,
    int m0, int n0, int mode)
{
    const int K = EMBED;
    extern __shared__ __align__(16) char gsm[];
    uint32_t sbase = smem_u32(gsm);

    int tid  = threadIdx.x;
    int lane = tid & 31;
    int warp = tid >> 5;                 // 0..3
    int grp  = lane >> 2, thr4 = lane & 3;
    int m0w = (warp >> 1) * 64;
    int n0w = (warp & 1) * 64;

    float c[4][8][4];
    #pragma unroll
    for (int mi = 0; mi < 4; mi++)
        #pragma unroll
        for (int ni = 0; ni < 8; ni++)
            #pragma unroll
            for (int q = 0; q < 4; q++) c[mi][ni][q] = 0.f;

    auto issue = [&](int k0, int s) {
        #pragma unroll
        for (int i = 0; i < 8; i++) {
            int idx = tid + i*128;          // 0..1023
            int row = idx >> 3, seg = idx & 7;
            uint32_t doff = (uint32_t)(s*GSTAGE_B + row*144 + seg*16);
            const char* ga = (const char*)A + ((size_t)(m0 + row) * K + k0) * 2 + seg*16;
            asm volatile("cp.async.cg.shared.global [%0], [%1], 16;" :: "r"(sbase + doff), "l"(ga));
            const char* gw = (const char*)W + ((size_t)(n0 + row) * K + k0) * 2 + seg*16;
            asm volatile("cp.async.cg.shared.global [%0], [%1], 16;" :: "r"(sbase + doff + GAREG_B), "l"(gw));
        }
        asm volatile("cp.async.commit_group;" ::: "memory");
    };

    issue(0, 0);

    const int NCHUNK = K / 64;   // 16
    for (int ch = 0; ch < NCHUNK; ch++) {
        asm volatile("cp.async.wait_group 0;" ::: "memory");
        __syncthreads();
        if (ch + 1 < NCHUNK) issue((ch + 1) * 64, (ch + 1) & 1);

        const __half* As = (const __half*)(gsm + (ch & 1) * GSTAGE_B);
        const __half* Ws = (const __half*)(gsm + (ch & 1) * GSTAGE_B + GAREG_B);
        #pragma unroll
        for (int ks = 0; ks < 4; ks++) {
            int cc = thr4*2 + ks*16;
            uint32_t a[4][4];
            #pragma unroll
            for (int mi = 0; mi < 4; mi++) {
                int r = m0w + mi*16 + grp;
                a[mi][0] = *(const uint32_t*)(As + r*GHPITCH + cc);
                a[mi][1] = *(const uint32_t*)(As + (r+8)*GHPITCH + cc);
                a[mi][2] = *(const uint32_t*)(As + r*GHPITCH + cc + 8);
                a[mi][3] = *(const uint32_t*)(As + (r+8)*GHPITCH + cc + 8);
            }
            #pragma unroll
            for (int ni = 0; ni < 8; ni++) {
                int rn = n0w + ni*8 + grp;
                uint32_t b0 = *(const uint32_t*)(Ws + rn*GHPITCH + cc);
                uint32_t b1 = *(const uint32_t*)(Ws + rn*GHPITCH + cc + 8);
                #pragma unroll
                for (int mi = 0; mi < 4; mi++)
                    mma_f16(c[mi][ni], a[mi], b0, b1);
            }
        }
        __syncthreads();
    }

    #pragma unroll
    for (int mi = 0; mi < 4; mi++) {
        int rbase = m0 + m0w + mi * 16 + grp;
        #pragma unroll
        for (int ni = 0; ni < 8; ni++) {
            int col = n0 + n0w + ni * 8 + 2 * thr4;          // even
            float bv0 = bias[col], bv1 = bias[col + 1];
            #pragma unroll
            for (int half = 0; half < 2; half++) {
                int m = rbase + half * 8;
                float v0 = c[mi][ni][half * 2 + 0] + bv0;
                float v1 = c[mi][ni][half * 2 + 1] + bv1;
                if (mode == 0) {
                    Cf[(size_t)m * EMBED + col]     = v0;
                    Cf[(size_t)m * EMBED + col + 1] = v1;
                } else {
                    int bb = m >> 11, t = m & 2047;
                    int hh = col >> 6, d = col & 63;
                    __half h0 = __float2half(v0), h1 = __float2half(v1);
                    __half l0v = __float2half(v0 - __half2float(h0));
                    __half l1v = __float2half(v1 - __half2float(h1));
                    if (mode == 1) {
                        size_t base = (((size_t)(bb * NHEAD + hh)) * SEQ + t) * HDIM + d;
                        __half2 hp = __halves2half2(h0, h1);
                        __half2 lp = __halves2half2(l0v, l1v);
                        reinterpret_cast<uint32_t*>(Ch)[base >> 1] = *reinterpret_cast<uint32_t*>(&hp);
                        reinterpret_cast<uint32_t*>(Cl)[base >> 1] = *reinterpret_cast<uint32_t*>(&lp);
                    } else {   // mode 2: transposed [B,H,D,T]
                        size_t o0 = (((size_t)(bb * NHEAD + hh)) * HDIM + d) * SEQ + t;
                        Ch[o0]       = h0;
                        Ch[o0 + SEQ] = h1;
                        Cl[o0]       = l0v;
                        Cl[o0 + SEQ] = l1v;
                    }
                }
            }
        }
    }
}

__global__ __launch_bounds__(128) void gemm_qkv(
    const float* __restrict__ bq, const float* __restrict__ bk, const float* __restrict__ bv)
{
    int z = blockIdx.z;
    const __half* A = (z == 0) ? g_qc : (z == 1) ? g_kc : g_vc;
    const __half* W = g_w4 + (size_t)z * EMBED * EMBED;
    const float* B = (z == 0) ? bq : (z == 1) ? bk : bv;
    __half* Ch = (z == 0) ? g_qh : (z == 1) ? g_kh : g_vh;
    __half* Cl = (z == 0) ? g_ql : (z == 1) ? g_kl : g_vl;
    gemm_body(A, W, B, nullptr, Ch, Cl, blockIdx.y * 128, blockIdx.x * 128,
              (z == 2) ? 2 : 1);
}

// gemm_out: A = attention output as fp16 hi+lo; C = A_hi@W^T + A_lo@W^T + bias.
// Two single-term passes give fp32-grade A accuracy; W is 11-bit exact.
__global__ __launch_bounds__(128) void gemm_out(
    const float* __restrict__ bias, float* __restrict__ C)
{
    const int K = EMBED;
    extern __shared__ __align__(16) char gsm[];
    uint32_t sbase = smem_u32(gsm);
    const __half* W = g_w4 + (size_t)3 * EMBED * EMBED;
    int m0 = blockIdx.y * 128, n0 = blockIdx.x * 128;

    int tid  = threadIdx.x;
    int lane = tid & 31;
    int warp = tid >> 5;
    int grp  = lane >> 2, thr4 = lane & 3;
    int m0w = (warp >> 1) * 64;
    int n0w = (warp & 1) * 64;

    float c[4][8][4];
    #pragma unroll
    for (int mi = 0; mi < 4; mi++)
        #pragma unroll
        for (int ni = 0; ni < 8; ni++)
            #pragma unroll
            for (int q = 0; q < 4; q++) c[mi][ni][q] = 0.f;

    // stage: Ah | Al | W  (3 regions of 18432 B) x 2 stages
    auto issue = [&](int k0, int s) {
        #pragma unroll
        for (int i = 0; i < 8; i++) {
            int idx = tid + i*128;
            int row = idx >> 3, seg = idx & 7;
            uint32_t doff = (uint32_t)(s*3*GAREG_B + row*144 + seg*16);
            const char* gah = (const char*)g_aoh + ((size_t)(m0 + row) * K + k0) * 2 + seg*16;
            asm volatile("cp.async.cg.shared.global [%0], [%1], 16;" :: "r"(sbase + doff), "l"(gah));
            const char* gal = (const char*)g_aol + ((size_t)(m0 + row) * K + k0) * 2 + seg*16;
            asm volatile("cp.async.cg.shared.global [%0], [%1], 16;" :: "r"(sbase + doff + GAREG_B), "l"(gal));
            const char* gw = (const char*)W + ((size_t)(n0 + row) * K + k0) * 2 + seg*16;
            asm volatile("cp.async.cg.shared.global [%0], [%1], 16;" :: "r"(sbase + doff + 2*GAREG_B), "l"(gw));
        }
        asm volatile("cp.async.commit_group;" ::: "memory");
    };

    issue(0, 0);

    const int NCHUNK = K / 64;   // 16
    for (int ch = 0; ch < NCHUNK; ch++) {
        asm volatile("cp.async.wait_group 0;" ::: "memory");
        __syncthreads();
        if (ch + 1 < NCHUNK) issue((ch + 1) * 64, (ch + 1) & 1);

        const __half* Ah = (const __half*)(gsm + (ch & 1) * 3*GAREG_B);
        const __half* Al = Ah + GAREG_B/2;
        const __half* Ws = Ah + GAREG_B;     // (2 regions of halves)
        #pragma unroll
        for (int ks = 0; ks < 4; ks++) {
            int cc = thr4*2 + ks*16;
            uint32_t ah[4][4], al[4][4];
            #pragma unroll
            for (int mi = 0; mi < 4; mi++) {
                int r = m0w + mi*16 + grp;
                ah[mi][0] = *(const uint32_t*)(Ah + r*GHPITCH + cc);
                ah[mi][1] = *(const uint32_t*)(Ah + (r+8)*GHPITCH + cc);
                ah[mi][2] = *(const uint32_t*)(Ah + r*GHPITCH + cc + 8);
                ah[mi][3] = *(const uint32_t*)(Ah + (r+8)*GHPITCH + cc + 8);
                al[mi][0] = *(const uint32_t*)(Al + r*GHPITCH + cc);
                al[mi][1] = *(const uint32_t*)(Al + (r+8)*GHPITCH + cc);
                al[mi][2] = *(const uint32_t*)(Al + r*GHPITCH + cc + 8);
                al[mi][3] = *(const uint32_t*)(Al + (r+8)*GHPITCH + cc + 8);
            }
            #pragma unroll
            for (int ni = 0; ni < 8; ni++) {
                int rn = n0w + ni*8 + grp;
                uint32_t b0 = *(const uint32_t*)(Ws + rn*GHPITCH + cc);
                uint32_t b1 = *(const uint32_t*)(Ws + rn*GHPITCH + cc + 8);
                #pragma unroll
                for (int mi = 0; mi < 4; mi++) {
                    mma_f16(c[mi][ni], ah[mi], b0, b1);
                    mma_f16(c[mi][ni], al[mi], b0, b1);
                }
            }
        }
        __syncthreads();
    }

    #pragma unroll
    for (int mi = 0; mi < 4; mi++) {
        int rbase = m0 + m0w + mi * 16 + grp;
        #pragma unroll
        for (int ni = 0; ni < 8; ni++) {
            int col = n0 + n0w + ni * 8 + 2 * thr4;
            float bv0 = bias[col], bv1 = bias[col + 1];
            #pragma unroll
            for (int half = 0; half < 2; half++) {
                int m = rbase + half * 8;
                C[(size_t)m * EMBED + col]     = c[mi][ni][half*2+0] + bv0;
                C[(size_t)m * EMBED + col + 1] = c[mi][ni][half*2+1] + bv1;
            }
        }
    }
}
#define GEMM_OUT_SMEM (2*3*GAREG_B)   // 110592

// ---------------------------------------------------------------------------
// Flash attention (R15-proven, 256 thr / 128 Q rows): fp16 split mma;
// ex2.approx.f16x2; l via ones-mma; 2-stage cp.async staging.
// Epilogue writes fp16 hi/lo for gemm_out.
// ---------------------------------------------------------------------------
#define FPITCH 72
#define FSM_STAGE0   36864
#define FSM_STAGE_SZ 36864
#define FSM_REG      9216
#define FSM_MASK     (FSM_STAGE0 + 2*FSM_STAGE_SZ)   // 110592
#define FLASH_SMEM   (FSM_MASK + 2*256)              // 111104

__global__ __launch_bounds__(256, 1) void flash_attn_mma()
{
    extern __shared__ __align__(16) char smraw[];
    __half* sQh = (__half*)smraw;
    __half* sQl = sQh + 128*FPITCH;
    uint32_t sb = smem_u32(smraw);

    int tid  = threadIdx.x;
    int lane = tid & 31, warp = tid >> 5;
    int grp  = lane >> 2, thr4 = lane & 3;
    int qt = (int)gridDim.x - 1 - (int)blockIdx.x;   // heavy tiles first
    int h = blockIdx.y, b = blockIdx.z;
    int qbase = qt * 128;

    size_t headoff = ((size_t)(b*NHEAD + h))*SEQ*HDIM;
    const uint32_t* Qh32 = (const uint32_t*)g_qh + (headoff + (size_t)qbase*HDIM)/2;
    const uint32_t* Ql32 = (const uint32_t*)g_ql + (headoff + (size_t)qbase*HDIM)/2;
    const char* khg = (const char*)g_kh + headoff*2;
    const char* klg = (const char*)g_kl + headoff*2;
    const char* vhg = (const char*)g_vh + headoff*2;   // [D][T] layout
    const char* vlg = (const char*)g_vl + headoff*2;
    const char* mfg = (const char*)(g_maskf + (size_t)b*SEQ);

    const int ntiles = 2*qt + 2;

    auto issue = [&](int jt) {
        int st = jt & 1;
        int s0 = jt * 64;
        uint32_t base = sb + FSM_STAGE0 + st*FSM_STAGE_SZ;
        #pragma unroll
        for (int i = 0; i < 2; i++) {
            int c = tid + i*256;            // 0..511
            int row = c >> 3;
            int o16 = (c & 7) * 16;
            uint32_t doff = (uint32_t)(row*144 + o16);
            const char* ksrc = khg + (size_t)(s0 + row)*128 + o16;
            asm volatile("cp.async.cg.shared.global [%0], [%1], 16;" :: "r"(base + doff), "l"(ksrc));
            const char* ksrc2 = klg + (size_t)(s0 + row)*128 + o16;
            asm volatile("cp.async.cg.shared.global [%0], [%1], 16;" :: "r"(base + FSM_REG + doff), "l"(ksrc2));
            const char* vsrc = vhg + (size_t)row*(SEQ*2) + s0*2 + o16;
            asm volatile("cp.async.cg.shared.global [%0], [%1], 16;" :: "r"(base + 2*FSM_REG + doff), "l"(vsrc));
            const char* vsrc2 = vlg + (size_t)row*(SEQ*2) + s0*2 + o16;
            asm volatile("cp.async.cg.shared.global [%0], [%1], 16;" :: "r"(base + 3*FSM_REG + doff), "l"(vsrc2));
        }
        if (tid < 16) {
            uint32_t dm = sb + FSM_MASK + st*256 + tid*16;
            const char* ms = mfg + (size_t)s0*4 + tid*16;
            asm volatile("cp.async.cg.shared.global [%0], [%1], 16;" :: "r"(dm), "l"(ms));
        }
        asm volatile("cp.async.commit_group;" ::: "memory");
    };

    issue(0);

    #pragma unroll
    for (int i = 0; i < 8; i++) {
        int e = tid + i*256;
        int r = e >> 4, c4 = (e & 15) << 2;
        int gi = (r*HDIM + c4) >> 1;
        *reinterpret_cast<uint2*>(sQh + r*FPITCH + c4) = *reinterpret_cast<const uint2*>(Qh32 + gi);
        *reinterpret_cast<uint2*>(sQl + r*FPITCH + c4) = *reinterpret_cast<const uint2*>(Ql32 + gi);
    }
    __syncthreads();

    uint32_t qh[4][4], ql[4][4];
    {
        int rl = warp*16 + grp;
        #pragma unroll
        for (int ks = 0; ks < 4; ks++) {
            int cc = thr4*2 + ks*16;
            qh[ks][0] = *(const uint32_t*)(sQh + rl*FPITCH + cc);
            qh[ks][1] = *(const uint32_t*)(sQh + (rl+8)*FPITCH + cc);
            qh[ks][2] = *(const uint32_t*)(sQh + rl*FPITCH + cc + 8);
            qh[ks][3] = *(const uint32_t*)(sQh + (rl+8)*FPITCH + cc + 8);
            ql[ks][0] = *(const uint32_t*)(sQl + rl*FPITCH + cc);
            ql[ks][1] = *(const uint32_t*)(sQl + (rl+8)*FPITCH + cc);
            ql[ks][2] = *(const uint32_t*)(sQl + rl*FPITCH + cc + 8);
            ql[ks][3] = *(const uint32_t*)(sQl + (rl+8)*FPITCH + cc + 8);
        }
    }

    int row0 = qbase + warp*16 + grp;
    int row1 = row0 + 8;

    float m0 = -1e30f, m1 = -1e30f, l0 = 0.f, l1 = 0.f;
    float o[8][4];
    #pragma unroll
    for (int j = 0; j < 8; j++)
        #pragma unroll
        for (int q = 0; q < 4; q++) o[j][q] = 0.f;

    const float L2E = 1.4426950408889634f;
    const uint32_t ONES2 = 0x3C003C00u;

    for (int jt = 0; jt < ntiles; jt++) {
        int s0 = jt * 64;
        int st = jt & 1;
        asm volatile("cp.async.wait_group 0;" ::: "memory");
        __syncthreads();
        if (jt + 1 < ntiles) issue(jt + 1);

        __half* sKh = (__half*)(smraw + FSM_STAGE0 + st*FSM_STAGE_SZ);
        __half* sKl = sKh + FSM_REG/2;
        __half* sVh = sKh + FSM_REG;
        __half* sVl = sKh + 3*FSM_REG/2;
        float* mfs = (float*)(smraw + FSM_MASK + st*256);

        float s[8][4];
        #pragma unroll
        for (int j = 0; j < 8; j++)
            #pragma unroll
            for (int q = 0; q < 4; q++) s[j][q] = 0.f;

        #pragma unroll
        for (int ks = 0; ks < 4; ks++) {
            int cc = thr4*2 + ks*16;
            #pragma unroll
            for (int j = 0; j < 8; j++) {
                int n = j*8 + grp;
                uint32_t bh0 = *(const uint32_t*)(sKh + n*FPITCH + cc);
                uint32_t bh1 = *(const uint32_t*)(sKh + n*FPITCH + cc + 8);
                uint32_t bl0 = *(const uint32_t*)(sKl + n*FPITCH + cc);
                uint32_t bl1 = *(const uint32_t*)(sKl + n*FPITCH + cc + 8);
                mma_f16(s[j], qh[ks], bh0, bh1);
                mma_f16(s[j], qh[ks], bl0, bl1);
                mma_f16(s[j], ql[ks], bh0, bh1);
            }
        }

        bool diag = (jt >= 2*qt);
        float nm0 = m0, nm1 = m1;
        #pragma unroll
        for (int j = 0; j < 8; j++) {
            int cb = 8*j + 2*thr4;
            float f0 = mfs[cb], f1 = mfs[cb+1];
            float v00 = fmaf(s[j][0], 0.125f, f0);
            float v01 = fmaf(s[j][1], 0.125f, f1);
            float v10 = fmaf(s[j][2], 0.125f, f0);
            float v11 = fmaf(s[j][3], 0.125f, f1);
            if (diag) {
                int ca = s0 + cb;
                if (ca     > row0) v00 = -1e30f;
                if (ca + 1 > row0) v01 = -1e30f;
                if (ca     > row1) v10 = -1e30f;
                if (ca + 1 > row1) v11 = -1e30f;
            }
            s[j][0] = v00; s[j][1] = v01; s[j][2] = v10; s[j][3] = v11;
            nm0 = fmaxf(nm0, fmaxf(v00, v01));
            nm1 = fmaxf(nm1, fmaxf(v10, v11));
        }
        nm0 = fmaxf(nm0, __shfl_xor_sync(0xffffffffu, nm0, 1));
        nm0 = fmaxf(nm0, __shfl_xor_sync(0xffffffffu, nm0, 2));
        nm1 = fmaxf(nm1, __shfl_xor_sync(0xffffffffu, nm1, 1));
        nm1 = fmaxf(nm1, __shfl_xor_sync(0xffffffffu, nm1, 2));

        float c0 = __expf(m0 - nm0), c1 = __expf(m1 - nm1);
        m0 = nm0; m1 = nm1;
        float mb0 = m0 * L2E, mb1 = m1 * L2E;

        uint32_t pr[8], ps[8];
        #pragma unroll
        for (int j = 0; j < 8; j++) {
            float t00 = fmaf(s[j][0], L2E, -mb0);
            float t01 = fmaf(s[j][1], L2E, -mb0);
            float t10 = fmaf(s[j][2], L2E, -mb1);
            float t11 = fmaf(s[j][3], L2E, -mb1);
            uint32_t ta, tb;
            asm("cvt.rn.f16x2.f32 %0, %1, %2;" : "=r"(ta) : "f"(t01), "f"(t00));
            asm("cvt.rn.f16x2.f32 %0, %1, %2;" : "=r"(tb) : "f"(t11), "f"(t10));
            asm("ex2.approx.f16x2 %0, %1;" : "=r"(pr[j]) : "r"(ta));
            asm("ex2.approx.f16x2 %0, %1;" : "=r"(ps[j]) : "r"(tb));
        }

        float lacc[4] = {0.f, 0.f, 0.f, 0.f};
        #pragma unroll
        for (int ks = 0; ks < 4; ks++) {
            uint32_t a[4] = {pr[2*ks], ps[2*ks], pr[2*ks+1], ps[2*ks+1]};
            mma_f16(lacc, a, ONES2, ONES2);
        }
        l0 = l0*c0 + lacc[0];
        l1 = l1*c1 + lacc[2];

        #pragma unroll
        for (int j = 0; j < 8; j++) {
            o[j][0] *= c0; o[j][1] *= c0;
            o[j][2] *= c1; o[j][3] *= c1;
        }

        #pragma unroll
        for (int ks = 0; ks < 4; ks++) {
            uint32_t a[4] = {pr[2*ks], ps[2*ks], pr[2*ks+1], ps[2*ks+1]};
            int cc = thr4*2 + ks*16;
            #pragma unroll
            for (int j = 0; j < 8; j++) {
                int n = j*8 + grp;
                uint32_t vh0 = *(const uint32_t*)(sVh + n*FPITCH + cc);
                uint32_t vh1 = *(const uint32_t*)(sVh + n*FPITCH + cc + 8);
                uint32_t vl0 = *(const uint32_t*)(sVl + n*FPITCH + cc);
                uint32_t vl1 = *(const uint32_t*)(sVl + n*FPITCH + cc + 8);
                mma_f16(o[j], a, vh0, vh1);
                mma_f16(o[j], a, vl0, vl1);
            }
        }
    }

    // ---- epilogue: write fp16 hi/lo [B,T,E] for gemm_out ----
    float inv0 = 1.f / l0, inv1 = 1.f / l1;
    size_t e0 = ((size_t)(b*SEQ) + row0)*EMBED + h*HDIM;
    size_t e1 = ((size_t)(b*SEQ) + row1)*EMBED + h*HDIM;
    #pragma unroll
    for (int j = 0; j < 8; j++) {
        int col = 8*j + 2*thr4;
        float a0 = o[j][0]*inv0, a1 = o[j][1]*inv0;
        float b0f = o[j][2]*inv1, b1f = o[j][3]*inv1;
        __half h00 = __float2half(a0), h01 = __float2half(a1);
        __half h10 = __float2half(b0f), h11 = __float2half(b1f);
        *(uint32_t*)(g_aoh + e0 + col) = packh2(a0, a1);
        *(uint32_t*)(g_aoh + e1 + col) = packh2(b0f, b1f);
        *(uint32_t*)(g_aol + e0 + col) = packh2(a0 - __half2float(h00), a1 - __half2float(h01));
        *(uint32_t*)(g_aol + e1 + col) = packh2(b0f - __half2float(h10), b1f - __half2float(h11));
    }
}

// ---------------------------------------------------------------------------
extern "C" void kernel_launch(void* const* d_in, const int* in_sizes, int n_in,
                              void* d_out, int out_size)
{
    const float* query = (const float*)d_in[0];
    const float* key   = (const float*)d_in[1];
    const float* value = (const float*)d_in[2];
    const unsigned char* kpm = (const unsigned char*)d_in[3];
    const float* Wq = (const float*)d_in[4];
    const float* bq = (const float*)d_in[5];
    const float* Wk = (const float*)d_in[6];
    const float* bk = (const float*)d_in[7];
    const float* Wv = (const float*)d_in[8];
    const float* bv = (const float*)d_in[9];
    const float* Wo = (const float*)d_in[10];
    const float* bo = (const float*)d_in[11];
    float* out = (float*)d_out;

    prepass<<<16384, 256>>>(query, key, value, Wq, Wk, Wv, Wo);
    mask_prep<<<16, 256>>>(kpm);

    cudaFuncSetAttribute(gemm_qkv, cudaFuncAttributeMaxDynamicSharedMemorySize, GEMM_SMEM);
    cudaFuncSetAttribute(gemm_out, cudaFuncAttributeMaxDynamicSharedMemorySize, GEMM_OUT_SMEM);

    dim3 gqkv(EMBED/128, MROWS/128, 3);   // (8, 32, 3)
    gemm_qkv<<<gqkv, 128, GEMM_SMEM>>>(bq, bk, bv);

    cudaFuncSetAttribute(flash_attn_mma, cudaFuncAttributeMaxDynamicSharedMemorySize, FLASH_SMEM);
    flash_attn_mma<<<dim3(SEQ/128, NHEAD, BATCH), 256, FLASH_SMEM>>>();

    dim3 gout(EMBED/128, MROWS/128);
    gemm_out<<<gout, 128, GEMM_OUT_SMEM>>>(bo, out);
}